// round 1
// baseline (speedup 1.0000x reference)
#include <cuda_runtime.h>

#define T_STEPS 2048
#define BATCH   512
#define NH      32
#define NC      5

typedef unsigned long long u64;

__device__ __forceinline__ float ex2a(float x) {
    float r; asm("ex2.approx.f32 %0, %1;" : "=f"(r) : "f"(x)); return r;
}
__device__ __forceinline__ float rcpa(float x) {
    float r; asm("rcp.approx.f32 %0, %1;" : "=f"(r) : "f"(x)); return r;
}
__device__ __forceinline__ u64 pack2(float lo, float hi) {
    u64 r; asm("mov.b64 %0, {%1, %2};" : "=l"(r) : "f"(lo), "f"(hi)); return r;
}
__device__ __forceinline__ void unpack2(u64 v, float& lo, float& hi) {
    asm("mov.b64 {%0, %1}, %2;" : "=f"(lo), "=f"(hi) : "l"(v));
}
__device__ __forceinline__ u64 fma2(u64 a, u64 b, u64 c) {
    u64 d; asm("fma.rn.f32x2 %0, %1, %2, %3;" : "=l"(d) : "l"(a), "l"(b), "l"(c)); return d;
}
__device__ __forceinline__ u64 add2(u64 a, u64 b) {
    u64 d; asm("add.rn.f32x2 %0, %1, %2;" : "=l"(d) : "l"(a), "l"(b)); return d;
}

// One SASS-visible step of the recurrence.
//  RDBUF/WRBUF: double-buffered per-warp r-vector in shared memory.
//  XES: register stage holding xe row for step t+1 (consumed -> accU(t+1)),
//       then refilled with xe row for step t+3 (address i3 = idx(t+3)).
//  TNEXT: clamped time index whose x[] entry we prefetch (becomes i3 three steps later).
#define STEP(RDBUF, WRBUF, XES, TNEXT)                                          \
  {                                                                             \
    __syncwarp();                                                               \
    const ulonglong2* rb16 = reinterpret_cast<const ulonglong2*>(RDBUF);        \
    u64 accA = accUp, accB = zerop;                                             \
    _Pragma("unroll")                                                           \
    for (int m = 0; m < 8; m++) {                                               \
        ulonglong2 rv = rb16[m];                                                \
        accA = fma2(rv.x, nwhp[2*m+0], accA);                                   \
        accB = fma2(rv.y, nwhp[2*m+1], accB);                                   \
    }                                                                           \
    u64 accs = add2(accA, accB);                                                \
    float zl, zh; unpack2(accs, zl, zh);                                        \
    float z = zl + zh;                                                          \
    float e = ex2a(z);                                                          \
    float r = rcpa(e + 1.0f);                                                   \
    (WRBUF)[j] = r;                                                             \
    rlast = r;                                                                  \
    /* off critical path: accU for step t+1 from staged xe */                   \
    u64 nu = basep;                                                             \
    _Pragma("unroll")                                                           \
    for (int m = 0; m < 8; m++) {                                               \
        nu = fma2(XES[m].x, wx2p[2*m+0], nu);                                   \
        nu = fma2(XES[m].y, wx2p[2*m+1], nu);                                   \
    }                                                                           \
    accUp = nu;                                                                 \
    /* prefetch embedding row for step t+3 (i3 loaded 3 steps ago) */           \
    {                                                                           \
        const ulonglong2* pe = emb16 + (long long)i3 * 8;                       \
        _Pragma("unroll")                                                       \
        for (int m = 0; m < 8; m++) XES[m] = __ldg(pe + m);                     \
    }                                                                           \
    i3 = i4; i4 = i5;                                                           \
    i5 = __ldg(xb + (TNEXT) * BATCH);                                           \
  }

__global__ void __launch_bounds__(128, 1) rnn_fused(
    const int*   __restrict__ x,      // (T, B) int32
    const float* __restrict__ emb,    // (32000, 32)
    const float* __restrict__ W_rnn,  // (64, 32): rows 0..31 = Wx, rows 32..63 = Wh
    const float* __restrict__ b_rnn,  // (32,)
    const float* __restrict__ W_cls,  // (32, 5)
    const float* __restrict__ b_cls,  // (5,)
    float*       __restrict__ out)    // (B, 5)
{
    __shared__ __align__(16) float rbuf[4][2][NH];

    const int warp = threadIdx.x >> 5;
    const int j    = threadIdx.x & 31;
    const int brow = (blockIdx.x << 2) + warp;

    const float S = 2.885390081777926814f;  // 2 * log2(e)

    // Per-lane weight columns, packed in k-pairs for fma.rn.f32x2.
    // z_j = S*a_j = accU_j - sum_k r_k * (2S*Wh[k][j])
    // accU_j = S*b_j + S*sum_k Wh[k][j] + sum_k xe_k * (S*Wx[k][j])
    u64 wx2p[NH/2];
    u64 nwhp[NH/2];
    float whsum = 0.f;
    #pragma unroll
    for (int m = 0; m < NH/2; m++) {
        float wx0 = W_rnn[(2*m+0)*NH + j];
        float wx1 = W_rnn[(2*m+1)*NH + j];
        float wh0 = W_rnn[(NH + 2*m+0)*NH + j];
        float wh1 = W_rnn[(NH + 2*m+1)*NH + j];
        whsum += S * (wh0 + wh1);
        wx2p[m] = pack2(S * wx0, S * wx1);
        nwhp[m] = pack2(-2.f * S * wh0, -2.f * S * wh1);
    }
    const u64 basep = pack2(S * b_rnn[j] + whsum, 0.f);
    const u64 zerop = pack2(0.f, 0.f);

    const int* xb = x + brow;
    const ulonglong2* emb16 = reinterpret_cast<const ulonglong2*>(emb);

    // ---- prologue: prime idx + embedding pipelines ----
    int id0 = __ldg(xb + 0 * BATCH);
    int id1 = __ldg(xb + 1 * BATCH);
    int id2 = __ldg(xb + 2 * BATCH);
    int i3  = __ldg(xb + 3 * BATCH);
    int i4  = __ldg(xb + 4 * BATCH);
    int i5  = __ldg(xb + 5 * BATCH);

    u64 accUp;
    {
        const ulonglong2* p0 = emb16 + (long long)id0 * 8;
        u64 a = basep;
        #pragma unroll
        for (int m = 0; m < 8; m++) {
            ulonglong2 v = __ldg(p0 + m);
            a = fma2(v.x, wx2p[2*m+0], a);
            a = fma2(v.y, wx2p[2*m+1], a);
        }
        accUp = a;  // accU for step 0
    }

    ulonglong2 xeA[8], xeB[8];
    {
        const ulonglong2* p1 = emb16 + (long long)id1 * 8;
        const ulonglong2* p2 = emb16 + (long long)id2 * 8;
        #pragma unroll
        for (int m = 0; m < 8; m++) xeA[m] = __ldg(p1 + m);  // xe(1)
        #pragma unroll
        for (int m = 0; m < 8; m++) xeB[m] = __ldg(p2 + m);  // xe(2)
    }

    float* buf0 = &rbuf[warp][0][0];
    float* buf1 = &rbuf[warp][1][0];
    buf0[j] = 0.5f;   // h_{-1} = 0  ->  r = (1-h)/2 = 0.5

    float rlast = 0.5f;

    // ---- main recurrence: 2 steps per iteration (fixed double-buffer parity) ----
    for (int t = 0; t < T_STEPS; t += 2) {
        int t6 = (t + 6 < T_STEPS) ? (t + 6) : (T_STEPS - 1);
        STEP(buf0, buf1, xeA, t6);
        int t7 = (t + 7 < T_STEPS) ? (t + 7) : (T_STEPS - 1);
        STEP(buf1, buf0, xeB, t7);
    }

    // ---- epilogue: y = h_final @ W_cls + b_cls ----
    float h = fmaf(-2.f, rlast, 1.f);
    #pragma unroll
    for (int c = 0; c < NC; c++) {
        float v = h * __ldg(W_cls + j * NC + c);
        #pragma unroll
        for (int off = 16; off; off >>= 1)
            v += __shfl_xor_sync(0xffffffffu, v, off);
        if (j == 0) out[brow * NC + c] = v + __ldg(b_cls + c);
    }
}

extern "C" void kernel_launch(void* const* d_in, const int* in_sizes, int n_in,
                              void* d_out, int out_size) {
    (void)in_sizes; (void)n_in; (void)out_size;
    rnn_fused<<<BATCH / 4, 128>>>(
        (const int*)d_in[0],
        (const float*)d_in[1],
        (const float*)d_in[2],
        (const float*)d_in[3],
        (const float*)d_in[4],
        (const float*)d_in[5],
        (float*)d_out);
}